// round 1
// baseline (speedup 1.0000x reference)
#include <cuda_runtime.h>
#include <math.h>

#define NROWS (64*9*374)      // 215424 rows of F=128
#define BT    (64*9)          // 576 (b,t) groups
#define RR    374
#define KSEL  299
#define EPS_TINY 1.17549435082228750797e-38f

// scratch (static device memory — no runtime allocation)
__device__ __align__(16) float g_local[NROWS*64];   // gelu(h1)[:, 0:64]
__device__ __align__(16) float g_hi[NROWS*64];      // gelu(h1)[:, 64:128]
__device__ float g_gcon[BT*32];                     // glob @ w2[64:,:]
__device__ float g_scores[NROWS];                   // score + gumbel

__device__ __forceinline__ float gelu_exact(float x) {
    return 0.5f * x * (1.0f + erff(x * 0.70710678118654752440f));
}

// ---------------------------------------------------------------------------
// Kernel 1: per-row LayerNorm + GEMM1 (128x128) + bias + exact GELU.
// Block: 128 rows x 128 cols tile, 256 threads, 8x8 register microtile.
// ---------------------------------------------------------------------------
__global__ void __launch_bounds__(256) k1_ln_gemm1(
    const float* __restrict__ x, const float* __restrict__ ln_w,
    const float* __restrict__ ln_b, const float* __restrict__ w1,
    const float* __restrict__ b1)
{
    extern __shared__ float sm[];
    float* w1s = sm;               // 128*128
    float* xs  = sm + 128*128;     // 128 rows, stride 132 (aligned float4)

    const int t  = threadIdx.x;
    const int R0 = blockIdx.x * 128;

    // stage w1 into smem
    {
        const float4* w4 = (const float4*)w1;
        float4* s4 = (float4*)w1s;
        #pragma unroll
        for (int i = 0; i < 16; i++) s4[i*256 + t] = w4[i*256 + t];
    }

    // layernorm: each warp handles 16 rows
    {
        const int lane = t & 31, w = t >> 5;
        float4 lw = ((const float4*)ln_w)[lane];
        float4 lb = ((const float4*)ln_b)[lane];
        for (int rr = 0; rr < 16; rr++) {
            int r = w*16 + rr;
            float4 xv = ((const float4*)x)[(size_t)(R0 + r)*32 + lane];
            float s = xv.x + xv.y + xv.z + xv.w;
            #pragma unroll
            for (int o = 16; o; o >>= 1) s += __shfl_xor_sync(0xffffffffu, s, o);
            float m = s * (1.0f/128.0f);
            float dx = xv.x - m, dy = xv.y - m, dz = xv.z - m, dw = xv.w - m;
            float q = dx*dx + dy*dy + dz*dz + dw*dw;
            #pragma unroll
            for (int o = 16; o; o >>= 1) q += __shfl_xor_sync(0xffffffffu, q, o);
            float rs = rsqrtf(q * (1.0f/128.0f) + 1e-5f);
            float4 y;
            y.x = dx*rs*lw.x + lb.x;
            y.y = dy*rs*lw.y + lb.y;
            y.z = dz*rs*lw.z + lb.z;
            y.w = dw*rs*lw.w + lb.w;
            *(float4*)(xs + r*132 + lane*4) = y;
        }
    }
    __syncthreads();

    const int ty = t >> 4, tx = t & 15;
    float acc[8][8];
    #pragma unroll
    for (int i = 0; i < 8; i++)
        #pragma unroll
        for (int j = 0; j < 8; j++) acc[i][j] = 0.0f;

    #pragma unroll 2
    for (int k = 0; k < 128; k++) {
        float a[8];
        #pragma unroll
        for (int i = 0; i < 8; i++) a[i] = xs[(ty*8 + i)*132 + k];
        float4 p0 = ((const float4*)w1s)[k*32 + tx*2];
        float4 p1 = ((const float4*)w1s)[k*32 + tx*2 + 1];
        float bb[8] = {p0.x, p0.y, p0.z, p0.w, p1.x, p1.y, p1.z, p1.w};
        #pragma unroll
        for (int i = 0; i < 8; i++)
            #pragma unroll
            for (int j = 0; j < 8; j++)
                acc[i][j] += a[i] * bb[j];
    }

    float bv[8];
    #pragma unroll
    for (int j = 0; j < 8; j++) bv[j] = b1[tx*8 + j];

    if (tx < 8) {            // local half: cols [0,64)
        #pragma unroll
        for (int i = 0; i < 8; i++) {
            size_t rg = (size_t)(R0 + ty*8 + i);
            float4 h0, h1;
            h0.x = gelu_exact(acc[i][0] + bv[0]);
            h0.y = gelu_exact(acc[i][1] + bv[1]);
            h0.z = gelu_exact(acc[i][2] + bv[2]);
            h0.w = gelu_exact(acc[i][3] + bv[3]);
            h1.x = gelu_exact(acc[i][4] + bv[4]);
            h1.y = gelu_exact(acc[i][5] + bv[5]);
            h1.z = gelu_exact(acc[i][6] + bv[6]);
            h1.w = gelu_exact(acc[i][7] + bv[7]);
            *(float4*)(g_local + rg*64 + tx*8)     = h0;
            *(float4*)(g_local + rg*64 + tx*8 + 4) = h1;
        }
    } else {                 // global half: cols [64,128) -> g_hi
        int c0 = tx*8 - 64;
        #pragma unroll
        for (int i = 0; i < 8; i++) {
            size_t rg = (size_t)(R0 + ty*8 + i);
            float4 h0, h1;
            h0.x = gelu_exact(acc[i][0] + bv[0]);
            h0.y = gelu_exact(acc[i][1] + bv[1]);
            h0.z = gelu_exact(acc[i][2] + bv[2]);
            h0.w = gelu_exact(acc[i][3] + bv[3]);
            h1.x = gelu_exact(acc[i][4] + bv[4]);
            h1.y = gelu_exact(acc[i][5] + bv[5]);
            h1.z = gelu_exact(acc[i][6] + bv[6]);
            h1.w = gelu_exact(acc[i][7] + bv[7]);
            *(float4*)(g_hi + rg*64 + c0)     = h0;
            *(float4*)(g_hi + rg*64 + c0 + 4) = h1;
        }
    }
}

// ---------------------------------------------------------------------------
// Kernel glob: deterministic mean over R of g_hi, then glob @ w2[64:,:].
// One block per (b,t), 64 threads.
// ---------------------------------------------------------------------------
__global__ void __launch_bounds__(64) k_glob(const float* __restrict__ w2)
{
    __shared__ float gl[64];
    const int bt = blockIdx.x, c = threadIdx.x;
    const float* base = g_hi + (size_t)bt * RR * 64 + c;
    float s = 0.0f;
    #pragma unroll 4
    for (int r = 0; r < RR; r++) s += base[(size_t)r * 64];
    gl[c] = s / 374.0f;
    __syncthreads();
    if (c < 32) {
        float a = 0.0f;
        #pragma unroll
        for (int k = 0; k < 64; k++) a += gl[k] * w2[(64 + k)*32 + c];
        g_gcon[bt*32 + c] = a;
    }
}

// ---------------------------------------------------------------------------
// Kernel 2: per-element local@w2[:64] + gcon + b2 -> GELU -> w3 head ->
// softmax(2) -> score + Gumbel(u) -> g_scores.
// ---------------------------------------------------------------------------
__global__ void __launch_bounds__(256) k2_scores(
    const float* __restrict__ w2, const float* __restrict__ b2,
    const float* __restrict__ w3, const float* __restrict__ b3,
    const float* __restrict__ u)
{
    __shared__ float w2s[64*32];
    __shared__ float w3s[64];
    __shared__ float b2s[32];
    __shared__ float b3s[2];
    const int t = threadIdx.x;
    #pragma unroll
    for (int i = 0; i < 8; i++) w2s[i*256 + t] = w2[i*256 + t];
    if (t < 64) w3s[t] = w3[t];
    if (t < 32) b2s[t] = b2[t];
    if (t < 2)  b3s[t] = b3[t];
    __syncthreads();

    const int e = blockIdx.x*256 + t;
    if (e >= NROWS) return;
    const int bt = e / RR;

    float in[64];
    const float4* lp = (const float4*)(g_local + (size_t)e*64);
    #pragma unroll
    for (int i = 0; i < 16; i++) {
        float4 v = lp[i];
        in[4*i] = v.x; in[4*i+1] = v.y; in[4*i+2] = v.z; in[4*i+3] = v.w;
    }

    float acc[32];
    #pragma unroll
    for (int g = 0; g < 32; g++) acc[g] = b2s[g] + g_gcon[bt*32 + g];

    #pragma unroll
    for (int k = 0; k < 64; k++) {
        float v = in[k];
        #pragma unroll
        for (int g = 0; g < 32; g++) acc[g] += v * w2s[k*32 + g];
    }

    float z0 = b3s[0], z1 = b3s[1];
    #pragma unroll
    for (int g = 0; g < 32; g++) {
        float h = gelu_exact(acc[g]);
        z0 += h * w3s[2*g];
        z1 += h * w3s[2*g + 1];
    }
    float m  = fmaxf(z0, z1);
    float e0 = expf(z0 - m), e1 = expf(z1 - m);
    float score = e1 / (e0 + e1);

    float uu  = u[e];
    float gum = -logf(-logf(uu));
    g_scores[e] = score + gum;
}

// ---------------------------------------------------------------------------
// Kernel 3: 299-step subset-operator scan + stable top-K, one warp per (b,t).
// Lane holds 12 strided elements; softmax without max-shift (no overflow:
// s <= ~15); single reciprocal per step instead of 12 divisions.
// ---------------------------------------------------------------------------
__global__ void __launch_bounds__(32) k3_scan(float* __restrict__ out)
{
    __shared__ float ks[RR];
    const int bt = blockIdx.x, lane = threadIdx.x;

    float s[12], kh[12];
    #pragma unroll
    for (int j = 0; j < 12; j++) {
        int idx = j*32 + lane;
        s[j]  = (idx < RR) ? g_scores[(size_t)bt*RR + idx] : -INFINITY;
        kh[j] = 0.0f;
    }

    for (int it = 0; it < KSEL; it++) {
        float ex[12];
        float z = 0.0f;
        #pragma unroll
        for (int j = 0; j < 12; j++) { ex[j] = expf(s[j]); z += ex[j]; }
        #pragma unroll
        for (int o = 16; o; o >>= 1) z += __shfl_xor_sync(0xffffffffu, z, o);
        float rinv = 1.0f / z;
        if (it < KSEL - 1) {
            #pragma unroll
            for (int j = 0; j < 12; j++) {
                float oh = ex[j] * rinv;
                kh[j] += oh;
                s[j]  += logf(fmaxf(1.0f - oh, EPS_TINY));
            }
        } else {
            #pragma unroll
            for (int j = 0; j < 12; j++) kh[j] += ex[j] * rinv;
        }
    }

    // write prob + stage for ranking
    #pragma unroll
    for (int j = 0; j < 12; j++) {
        int idx = j*32 + lane;
        if (idx < RR) {
            out[(size_t)bt*RR + idx] = kh[j];
            ks[idx] = kh[j];
        }
    }
    __syncthreads();

    // stable top-K rank: higher value first, ties -> lower index first
    int rank[12];
    #pragma unroll
    for (int j = 0; j < 12; j++) rank[j] = 0;
    for (int i = 0; i < RR; i++) {
        float kv = ks[i];
        #pragma unroll
        for (int j = 0; j < 12; j++) {
            int idx = j*32 + lane;
            rank[j] += (kv > kh[j]) || (kv == kh[j] && i < idx);
        }
    }
    float* idx_out = out + (size_t)NROWS;
    #pragma unroll
    for (int j = 0; j < 12; j++) {
        int idx = j*32 + lane;
        if (idx < RR && rank[j] < KSEL)
            idx_out[(size_t)bt*KSEL + rank[j]] = (float)idx;
    }
}

// ---------------------------------------------------------------------------
extern "C" void kernel_launch(void* const* d_in, const int* in_sizes, int n_in,
                              void* d_out, int out_size)
{
    const float* x   = (const float*)d_in[0];
    const float* u   = (const float*)d_in[1];
    const float* lnw = (const float*)d_in[2];
    const float* lnb = (const float*)d_in[3];
    const float* w1  = (const float*)d_in[4];
    const float* b1  = (const float*)d_in[5];
    const float* w2  = (const float*)d_in[6];
    const float* b2  = (const float*)d_in[7];
    const float* w3  = (const float*)d_in[8];
    const float* b3  = (const float*)d_in[9];
    float* out = (float*)d_out;

    const size_t smem1 = (size_t)(128*128 + 128*132) * sizeof(float);  // 133120 B
    cudaFuncSetAttribute(k1_ln_gemm1, cudaFuncAttributeMaxDynamicSharedMemorySize,
                         (int)smem1);

    k1_ln_gemm1<<<NROWS/128, 256, smem1>>>(x, lnw, lnb, w1, b1);
    k_glob<<<BT, 64>>>(w2);
    k2_scores<<<(NROWS + 255)/256, 256>>>(w2, b2, w3, b3, u);
    k3_scan<<<BT, 32>>>(out);
}

// round 2
// speedup vs baseline: 1.7061x; 1.7061x over previous
#include <cuda_runtime.h>
#include <math.h>

#define NROWS (64*9*374)      // 215424 rows of F=128
#define BT    (64*9)          // 576 (b,t) groups
#define RR    374
#define KSEL  299
#define EPS_TINY 1.17549435082228750797e-38f

typedef unsigned long long u64;

// scratch (static device memory — no runtime allocation)
__device__ __align__(16) float g_local[NROWS*64];   // gelu(h1)[:, 0:64]
__device__ __align__(16) float g_hi[NROWS*64];      // gelu(h1)[:, 64:128]
__device__ float g_gcon[BT*32];                     // glob @ w2[64:,:]
__device__ float g_scores[NROWS];                   // score + gumbel

__device__ __forceinline__ u64 fma2(u64 a, u64 b, u64 c) {
    u64 d; asm("fma.rn.f32x2 %0,%1,%2,%3;" : "=l"(d) : "l"(a), "l"(b), "l"(c));
    return d;
}
__device__ __forceinline__ u64 pk2(float lo, float hi) {
    u64 r; asm("mov.b64 %0,{%1,%2};" : "=l"(r) : "f"(lo), "f"(hi));
    return r;
}
__device__ __forceinline__ void upk2(u64 v, float& lo, float& hi) {
    asm("mov.b64 {%0,%1},%2;" : "=f"(lo), "=f"(hi) : "l"(v));
}
__device__ __forceinline__ float gelu_exact(float x) {
    return 0.5f * x * (1.0f + erff(x * 0.70710678118654752440f));
}

// ---------------------------------------------------------------------------
// Kernel 1: per-row LayerNorm + GEMM1 (128x128) + bias + exact GELU.
// 64-row tiles, 256 threads, 4x8 microtile, f32x2 FMA paired over K.
// A pairs: xs row-major (consecutive k).  B pairs: w1 transposed (stride 130).
// Thread covers cols {tx, tx+16, ..., tx+112} -> conflict-free LDS.64.
// ---------------------------------------------------------------------------
__global__ void __launch_bounds__(256, 2) k1_ln_gemm1(
    const float* __restrict__ x, const float* __restrict__ ln_w,
    const float* __restrict__ ln_b, const float* __restrict__ w1,
    const float* __restrict__ b1)
{
    extern __shared__ float sm[];
    float* w1t = sm;               // [128 cols][130]  (w1t[c*130 + k] = w1[k,c])
    float* xs  = sm + 128*130;     // [64 rows][132]

    const int t  = threadIdx.x;
    const int R0 = blockIdx.x * 64;

    // stage w1 transposed into smem
    #pragma unroll
    for (int i = 0; i < 16; i++) {
        int id = i*256 + t;              // float4 id: k = id/32, c4 = (id%32)*4
        int k  = id >> 5, c4 = (id & 31) << 2;
        float4 v = ((const float4*)w1)[id];
        w1t[(c4+0)*130 + k] = v.x;
        w1t[(c4+1)*130 + k] = v.y;
        w1t[(c4+2)*130 + k] = v.z;
        w1t[(c4+3)*130 + k] = v.w;
    }

    // layernorm: 8 warps x 8 rows
    {
        const int lane = t & 31, w = t >> 5;
        float4 lw = ((const float4*)ln_w)[lane];
        float4 lb = ((const float4*)ln_b)[lane];
        #pragma unroll
        for (int rr = 0; rr < 8; rr++) {
            int r = w*8 + rr;
            float4 xv = ((const float4*)x)[(size_t)(R0 + r)*32 + lane];
            float s = xv.x + xv.y + xv.z + xv.w;
            #pragma unroll
            for (int o = 16; o; o >>= 1) s += __shfl_xor_sync(0xffffffffu, s, o);
            float m = s * (1.0f/128.0f);
            float dx = xv.x - m, dy = xv.y - m, dz = xv.z - m, dw = xv.w - m;
            float q = dx*dx + dy*dy + dz*dz + dw*dw;
            #pragma unroll
            for (int o = 16; o; o >>= 1) q += __shfl_xor_sync(0xffffffffu, q, o);
            float rs = rsqrtf(q * (1.0f/128.0f) + 1e-5f);
            float4 y;
            y.x = dx*rs*lw.x + lb.x;
            y.y = dy*rs*lw.y + lb.y;
            y.z = dz*rs*lw.z + lb.z;
            y.w = dw*rs*lw.w + lb.w;
            *(float4*)(xs + r*132 + lane*4) = y;
        }
    }
    __syncthreads();

    const int ty = t >> 4, tx = t & 15;       // rows ty*4+i, cols tx + j*16
    u64 acc[4][8];
    #pragma unroll
    for (int i = 0; i < 4; i++)
        #pragma unroll
        for (int j = 0; j < 8; j++) acc[i][j] = 0ULL;

    const u64* xsu = (const u64*)xs;          // row stride 66 u64
    #pragma unroll 8
    for (int k2 = 0; k2 < 64; k2++) {
        u64 a[4];
        #pragma unroll
        for (int i = 0; i < 4; i++) a[i] = xsu[(ty*4 + i)*66 + k2];
        u64 b[8];
        #pragma unroll
        for (int j = 0; j < 8; j++)
            b[j] = ((const u64*)(w1t + (tx + j*16)*130))[k2];
        #pragma unroll
        for (int i = 0; i < 4; i++)
            #pragma unroll
            for (int j = 0; j < 8; j++)
                acc[i][j] = fma2(a[i], b[j], acc[i][j]);
    }

    float bv[8];
    #pragma unroll
    for (int j = 0; j < 8; j++) bv[j] = b1[tx + j*16];

    #pragma unroll
    for (int i = 0; i < 4; i++) {
        size_t rg = (size_t)(R0 + ty*4 + i);
        #pragma unroll
        for (int j = 0; j < 4; j++) {         // cols tx+j*16 < 64 -> local
            float lo, hi; upk2(acc[i][j], lo, hi);
            g_local[rg*64 + tx + j*16] = gelu_exact(lo + hi + bv[j]);
        }
        #pragma unroll
        for (int j = 4; j < 8; j++) {         // cols >= 64 -> hi
            float lo, hi; upk2(acc[i][j], lo, hi);
            g_hi[rg*64 + tx + (j-4)*16] = gelu_exact(lo + hi + bv[j]);
        }
    }
}

// ---------------------------------------------------------------------------
// Kernel glob: deterministic mean over R of g_hi, then glob @ w2[64:,:].
// One block per (b,t), 256 threads (4-way R split for MLP).
// ---------------------------------------------------------------------------
__global__ void __launch_bounds__(256) k_glob(const float* __restrict__ w2)
{
    __shared__ float part[256];
    __shared__ float gl[64];
    const int bt = blockIdx.x, t = threadIdx.x;
    const int c = t & 63, seg = t >> 6;
    const float* base = g_hi + (size_t)bt * RR * 64 + c;
    float s = 0.0f;
    #pragma unroll 8
    for (int r = seg; r < RR; r += 4) s += base[(size_t)r * 64];
    part[t] = s;
    __syncthreads();
    if (t < 64)
        gl[t] = (part[t] + part[t+64] + part[t+128] + part[t+192]) * (1.0f/374.0f);
    __syncthreads();
    if (t < 32) {
        float a = 0.0f;
        #pragma unroll
        for (int k = 0; k < 64; k++) a += gl[k] * w2[(64 + k)*32 + t];
        g_gcon[bt*32 + t] = a;
    }
}

// ---------------------------------------------------------------------------
// Kernel 2: per-element local@w2[:64] (f32x2) + gcon + b2 -> GELU -> w3 head
// -> softmax(2) -> score + Gumbel(u) -> g_scores.
// ---------------------------------------------------------------------------
__global__ void __launch_bounds__(256) k2_scores(
    const float* __restrict__ w2, const float* __restrict__ b2,
    const float* __restrict__ w3, const float* __restrict__ b3,
    const float* __restrict__ u)
{
    __shared__ float w2s[64*32];
    __shared__ float w3s[64];
    __shared__ float b2s[32];
    __shared__ float b3s[2];
    const int t = threadIdx.x;
    #pragma unroll
    for (int i = 0; i < 8; i++) w2s[i*256 + t] = w2[i*256 + t];
    if (t < 64) w3s[t] = w3[t];
    if (t < 32) b2s[t] = b2[t];
    if (t < 2)  b3s[t] = b3[t];
    __syncthreads();

    const int e = blockIdx.x*256 + t;
    if (e >= NROWS) return;
    const int bt = e / RR;

    float in[64];
    const float4* lp = (const float4*)(g_local + (size_t)e*64);
    #pragma unroll
    for (int i = 0; i < 16; i++) {
        float4 v = lp[i];
        in[4*i] = v.x; in[4*i+1] = v.y; in[4*i+2] = v.z; in[4*i+3] = v.w;
    }

    const float* gc = g_gcon + bt*32;
    u64 acc[16];
    #pragma unroll
    for (int g2 = 0; g2 < 16; g2++)
        acc[g2] = pk2(b2s[2*g2] + gc[2*g2], b2s[2*g2+1] + gc[2*g2+1]);

    #pragma unroll 8
    for (int k = 0; k < 64; k++) {
        u64 aa = pk2(in[k], in[k]);
        const u64* wr = (const u64*)(w2s + k*32);
        #pragma unroll
        for (int g2 = 0; g2 < 16; g2++) acc[g2] = fma2(aa, wr[g2], acc[g2]);
    }

    float z0 = b3s[0], z1 = b3s[1];
    #pragma unroll
    for (int g2 = 0; g2 < 16; g2++) {
        float a0, a1; upk2(acc[g2], a0, a1);
        float h0 = gelu_exact(a0);
        float h1 = gelu_exact(a1);
        z0 += h0 * w3s[4*g2]     + h1 * w3s[4*g2 + 2];
        z1 += h0 * w3s[4*g2 + 1] + h1 * w3s[4*g2 + 3];
    }
    float m  = fmaxf(z0, z1);
    float e0 = expf(z0 - m), e1 = expf(z1 - m);
    float score = e1 / (e0 + e1);

    float uu  = u[e];
    float gum = -logf(-logf(uu));
    g_scores[e] = score + gum;
}

// ---------------------------------------------------------------------------
// Kernel 3: 299-step subset-operator scan + stable top-K, one warp per (b,t).
// Multiplicative form: exp(s + log(max(1-oh,EPS))) == exp(s)*max(1-oh,EPS),
// so maintain ex = exp(s) directly; no exp/log inside the loop at all.
// ---------------------------------------------------------------------------
__global__ void __launch_bounds__(32) k3_scan(float* __restrict__ out)
{
    __shared__ float ks[RR];
    const int bt = blockIdx.x, lane = threadIdx.x;

    float ex[12], kh[12];
    #pragma unroll
    for (int j = 0; j < 12; j++) {
        int idx = j*32 + lane;
        ex[j] = (idx < RR) ? expf(g_scores[(size_t)bt*RR + idx]) : 0.0f;
        kh[j] = 0.0f;
    }

    for (int it = 0; it < KSEL; it++) {
        float z = (((ex[0] + ex[1]) + (ex[2] + ex[3])) +
                   ((ex[4] + ex[5]) + (ex[6] + ex[7]))) +
                  ((ex[8] + ex[9]) + (ex[10] + ex[11]));
        #pragma unroll
        for (int o = 16; o; o >>= 1) z += __shfl_xor_sync(0xffffffffu, z, o);
        float rinv = 1.0f / z;
        if (it < KSEL - 1) {
            #pragma unroll
            for (int j = 0; j < 12; j++) {
                float oh = ex[j] * rinv;
                kh[j] += oh;
                ex[j] *= fmaxf(1.0f - oh, EPS_TINY);
            }
        } else {
            #pragma unroll
            for (int j = 0; j < 12; j++) kh[j] += ex[j] * rinv;
        }
    }

    // write prob + stage for ranking
    #pragma unroll
    for (int j = 0; j < 12; j++) {
        int idx = j*32 + lane;
        if (idx < RR) {
            out[(size_t)bt*RR + idx] = kh[j];
            ks[idx] = kh[j];
        }
    }
    __syncthreads();

    // stable top-K rank: higher value first, ties -> lower index first
    int rank[12];
    #pragma unroll
    for (int j = 0; j < 12; j++) rank[j] = 0;
    for (int i = 0; i < RR; i++) {
        float kv = ks[i];
        #pragma unroll
        for (int j = 0; j < 12; j++) {
            int idx = j*32 + lane;
            rank[j] += (kv > kh[j]) || (kv == kh[j] && i < idx);
        }
    }
    float* idx_out = out + (size_t)NROWS;
    #pragma unroll
    for (int j = 0; j < 12; j++) {
        int idx = j*32 + lane;
        if (idx < RR && rank[j] < KSEL)
            idx_out[(size_t)bt*KSEL + rank[j]] = (float)idx;
    }
}

// ---------------------------------------------------------------------------
extern "C" void kernel_launch(void* const* d_in, const int* in_sizes, int n_in,
                              void* d_out, int out_size)
{
    const float* x   = (const float*)d_in[0];
    const float* u   = (const float*)d_in[1];
    const float* lnw = (const float*)d_in[2];
    const float* lnb = (const float*)d_in[3];
    const float* w1  = (const float*)d_in[4];
    const float* b1  = (const float*)d_in[5];
    const float* w2  = (const float*)d_in[6];
    const float* b2  = (const float*)d_in[7];
    const float* w3  = (const float*)d_in[8];
    const float* b3  = (const float*)d_in[9];
    float* out = (float*)d_out;

    const size_t smem1 = (size_t)(128*130 + 64*132) * sizeof(float);  // 100352 B
    cudaFuncSetAttribute(k1_ln_gemm1, cudaFuncAttributeMaxDynamicSharedMemorySize,
                         (int)smem1);

    k1_ln_gemm1<<<NROWS/64, 256, smem1>>>(x, lnw, lnb, w1, b1);
    k_glob<<<BT, 256>>>(w2);
    k2_scores<<<(NROWS + 255)/256, 256>>>(w2, b2, w3, b3, u);
    k3_scan<<<BT, 32>>>(out);
}

// round 3
// speedup vs baseline: 1.9597x; 1.1487x over previous
#include <cuda_runtime.h>
#include <math.h>

#define NROWS (64*9*374)      // 215424 rows of F=128
#define BT    (64*9)          // 576 (b,t) groups
#define RR    374
#define KSEL  299
#define NBLK1 (NROWS/128)     // 1683 k1 blocks (exact)
#define EPS_TINY 1.17549435082228750797e-38f

typedef unsigned long long u64;

// scratch (static device memory — no runtime allocation)
__device__ __align__(16) float g_local[(size_t)NROWS*64]; // gelu(h1)[:, 0:64]
__device__ float g_part[NBLK1*128];                       // per-block hi partials [blk][side][64]
__device__ float g_gcon[BT*32];                           // glob @ w2[64:,:]
__device__ float g_scores[NROWS];                         // score + gumbel

__device__ __forceinline__ u64 fma2(u64 a, u64 b, u64 c) {
    u64 d; asm("fma.rn.f32x2 %0,%1,%2,%3;" : "=l"(d) : "l"(a), "l"(b), "l"(c));
    return d;
}
__device__ __forceinline__ void upk2(u64 v, float& lo, float& hi) {
    asm("mov.b64 {%0,%1},%2;" : "=f"(lo), "=f"(hi) : "l"(v));
}
__device__ __forceinline__ float frcp(float x) {
    float r; asm("rcp.approx.ftz.f32 %0,%1;" : "=f"(r) : "f"(x));
    return r;
}
__device__ __forceinline__ float gelu_exact(float x) {
    return 0.5f * x * (1.0f + erff(x * 0.70710678118654752440f));
}

// ---------------------------------------------------------------------------
// Kernel 1: LayerNorm + GEMM1 (128x128) + bias + GELU.
// 128-row tiles, 256 threads, 8x8 microtile, f32x2 paired over K.
// Crossbar-balanced: 16 LDS phases per 64 FFMA2 per warp.
// Local half -> g_local; hi half accumulated into per-(block,group) partials.
// ---------------------------------------------------------------------------
__global__ void __launch_bounds__(256) k1_ln_gemm1(
    const float* __restrict__ x, const float* __restrict__ ln_w,
    const float* __restrict__ ln_b, const float* __restrict__ w1,
    const float* __restrict__ b1)
{
    extern __shared__ float sm[];
    float* w1t = sm;                 // [128 cols][130]
    float* xs  = sm + 128*130;       // [128 rows][132]
    float* red = sm + 128*130 + 128*132;  // [2][64][16]

    const int t  = threadIdx.x;
    const int R0 = blockIdx.x * 128;

    // stage w1 transposed
    #pragma unroll
    for (int i = 0; i < 16; i++) {
        int id = i*256 + t;              // k = id/32, c4 = (id%32)*4
        int k  = id >> 5, c4 = (id & 31) << 2;
        float4 v = ((const float4*)w1)[id];
        w1t[(c4+0)*130 + k] = v.x;
        w1t[(c4+1)*130 + k] = v.y;
        w1t[(c4+2)*130 + k] = v.z;
        w1t[(c4+3)*130 + k] = v.w;
    }

    // layernorm: 8 warps x 16 rows
    {
        const int lane = t & 31, w = t >> 5;
        float4 lw = ((const float4*)ln_w)[lane];
        float4 lb = ((const float4*)ln_b)[lane];
        #pragma unroll
        for (int rr = 0; rr < 16; rr++) {
            int r = w*16 + rr;
            float4 xv = ((const float4*)x)[(size_t)(R0 + r)*32 + lane];
            float s = xv.x + xv.y + xv.z + xv.w;
            #pragma unroll
            for (int o = 16; o; o >>= 1) s += __shfl_xor_sync(0xffffffffu, s, o);
            float m = s * (1.0f/128.0f);
            float dx = xv.x - m, dy = xv.y - m, dz = xv.z - m, dw = xv.w - m;
            float q = dx*dx + dy*dy + dz*dz + dw*dw;
            #pragma unroll
            for (int o = 16; o; o >>= 1) q += __shfl_xor_sync(0xffffffffu, q, o);
            float rs = rsqrtf(q * (1.0f/128.0f) + 1e-5f);
            float4 y;
            y.x = dx*rs*lw.x + lb.x;
            y.y = dy*rs*lw.y + lb.y;
            y.z = dz*rs*lw.z + lb.z;
            y.w = dw*rs*lw.w + lb.w;
            *(float4*)(xs + r*132 + lane*4) = y;
        }
    }
    __syncthreads();

    const int ty = t >> 4, tx = t & 15;   // rows ty*8+i, cols tx + j*16
    u64 acc[8][8];
    #pragma unroll
    for (int i = 0; i < 8; i++)
        #pragma unroll
        for (int j = 0; j < 8; j++) acc[i][j] = 0ULL;

    const u64* xsu = (const u64*)xs;      // row stride 66 u64
    #pragma unroll 4
    for (int k2 = 0; k2 < 64; k2++) {
        u64 a[8];
        #pragma unroll
        for (int i = 0; i < 8; i++) a[i] = xsu[(ty*8 + i)*66 + k2];
        #pragma unroll
        for (int jh = 0; jh < 2; jh++) {
            u64 b[4];
            #pragma unroll
            for (int j = 0; j < 4; j++)
                b[j] = ((const u64*)(w1t + (tx + (jh*4 + j)*16)*130))[k2];
            #pragma unroll
            for (int i = 0; i < 8; i++)
                #pragma unroll
                for (int j = 0; j < 4; j++)
                    acc[i][jh*4 + j] = fma2(a[i], b[j], acc[i][jh*4 + j]);
        }
    }

    float bv[8];
    #pragma unroll
    for (int j = 0; j < 8; j++) bv[j] = b1[tx + j*16];

    const int g0 = R0 / RR;
    const int boundary = (g0 + 1) * RR;
    float part[2][4];
    #pragma unroll
    for (int sdd = 0; sdd < 2; sdd++)
        #pragma unroll
        for (int j = 0; j < 4; j++) part[sdd][j] = 0.0f;

    #pragma unroll
    for (int i = 0; i < 8; i++) {
        int rg = R0 + ty*8 + i;
        // local half: cols tx + j*16 (j<4)
        #pragma unroll
        for (int j = 0; j < 4; j++) {
            float lo, hi; upk2(acc[i][j], lo, hi);
            g_local[(size_t)rg*64 + tx + j*16] = gelu_exact(lo + hi + bv[j]);
        }
        // hi half: accumulate glob partial per group side
        int sd = (rg >= boundary) ? 1 : 0;
        #pragma unroll
        for (int j = 4; j < 8; j++) {
            float lo, hi; upk2(acc[i][j], lo, hi);
            float v = gelu_exact(lo + hi + bv[j]);
            if (sd) part[1][j-4] += v; else part[0][j-4] += v;
        }
    }

    // reduce hi partials across ty (red[side][col][ty])
    #pragma unroll
    for (int sdd = 0; sdd < 2; sdd++)
        #pragma unroll
        for (int j = 0; j < 4; j++)
            red[((sdd*64) + (tx + j*16))*16 + ty] = part[sdd][j];
    __syncthreads();
    if (t < 128) {
        const float* rp = red + t*16;
        float s = 0.0f;
        #pragma unroll
        for (int i = 0; i < 16; i++) s += rp[i];
        g_part[blockIdx.x*128 + t] = s;   // [blk][side(0/1)][col]
    }
}

// ---------------------------------------------------------------------------
// Kernel glob: combine per-block partials -> mean -> glob @ w2[64:,:].
// ---------------------------------------------------------------------------
__global__ void __launch_bounds__(64) k_glob(const float* __restrict__ w2)
{
    __shared__ float gl[64];
    const int g = blockIdx.x, c = threadIdx.x;
    const int b_start = (g * RR) >> 7;
    const int b_end   = (g * RR + RR - 1) >> 7;
    float s = 0.0f;
    for (int b = b_start; b <= b_end; b++) {
        int side = g - (b * 128) / RR;    // 0 or 1 by construction
        s += g_part[b*128 + side*64 + c];
    }
    gl[c] = s * (1.0f/374.0f);
    __syncthreads();
    if (c < 32) {
        float a = 0.0f;
        #pragma unroll
        for (int k = 0; k < 64; k++) a += gl[k] * w2[(64 + k)*32 + c];
        g_gcon[g*32 + c] = a;
    }
}

// ---------------------------------------------------------------------------
// Kernel 2: tiled GEMM (128 elements x 32 cols, K=64) + GELU + w3 head +
// softmax + Gumbel -> g_scores.  Thread = 8 elements x 2 cols (f32x2 over K).
// ---------------------------------------------------------------------------
__global__ void __launch_bounds__(256) k2_scores(
    const float* __restrict__ w2, const float* __restrict__ b2,
    const float* __restrict__ w3, const float* __restrict__ b3,
    const float* __restrict__ u)
{
    __shared__ float ins[128*68];    // elements, stride 68 (16B aligned)
    __shared__ float w2t[32*66];     // transposed w2[:64,:], stride 66
    __shared__ float hbuf[128*34];   // gelu outputs per element
    __shared__ float w3s[64];
    __shared__ float b2s[32];
    __shared__ float b3s[2];

    const int t  = threadIdx.x;
    const int E0 = blockIdx.x * 128;

    // stage inputs (float4) and transposed w2
    #pragma unroll
    for (int i = 0; i < 8; i++) {
        int id = i*256 + t;              // el = id/16, q = id%16
        int el = id >> 4, q = id & 15;
        float4 v = ((const float4*)g_local)[(size_t)(E0 + el)*16 + q];
        *(float4*)(ins + el*68 + q*4) = v;
    }
    #pragma unroll
    for (int i = 0; i < 8; i++) {
        int id = i*256 + t;              // k = id/32, c = id%32
        int k = id >> 5, c = id & 31;
        w2t[c*66 + k] = w2[id];
    }
    if (t < 64) w3s[t] = w3[t];
    if (t < 32) b2s[t] = b2[t];
    if (t < 2)  b3s[t] = b3[t];
    __syncthreads();

    const int ty = t >> 4, tx = t & 15;   // elements ty*8+i, cols {tx, tx+16}
    u64 acc[8][2];
    #pragma unroll
    for (int i = 0; i < 8; i++) { acc[i][0] = 0ULL; acc[i][1] = 0ULL; }

    const u64* insu = (const u64*)ins;    // el stride 34
    const u64* w2u0 = (const u64*)(w2t + tx*66);
    const u64* w2u1 = (const u64*)(w2t + (tx+16)*66);
    #pragma unroll 4
    for (int k2 = 0; k2 < 32; k2++) {
        u64 b0 = w2u0[k2], b1 = w2u1[k2];
        #pragma unroll
        for (int i = 0; i < 8; i++) {
            u64 a = insu[(ty*8 + i)*34 + k2];
            acc[i][0] = fma2(a, b0, acc[i][0]);
            acc[i][1] = fma2(a, b1, acc[i][1]);
        }
    }

    // epilogue: gelu(acc + b2 + gcon) -> hbuf
    #pragma unroll
    for (int i = 0; i < 8; i++) {
        int el = ty*8 + i;
        int bt = (E0 + el) / RR;
        const float* gc = g_gcon + bt*32;
        float lo, hi;
        upk2(acc[i][0], lo, hi);
        hbuf[el*34 + tx]      = gelu_exact(lo + hi + b2s[tx]      + gc[tx]);
        upk2(acc[i][1], lo, hi);
        hbuf[el*34 + tx + 16] = gelu_exact(lo + hi + b2s[tx + 16] + gc[tx + 16]);
    }
    __syncthreads();

    // head: one thread per element
    if (t < 128) {
        const float* h = hbuf + t*34;
        float z0 = b3s[0], z1 = b3s[1];
        #pragma unroll
        for (int g = 0; g < 32; g++) {
            float hv = h[g];
            z0 += hv * w3s[2*g];
            z1 += hv * w3s[2*g + 1];
        }
        float m  = fmaxf(z0, z1);
        float e0 = expf(z0 - m), e1 = expf(z1 - m);
        float score = e1 / (e0 + e1);
        float uu  = u[E0 + t];
        float gum = -logf(-logf(uu));
        g_scores[E0 + t] = score + gum;
    }
}

// ---------------------------------------------------------------------------
// Kernel 3: 299-step subset-operator scan + stable top-K, one warp per (b,t).
// Multiplicative form; rcp.approx on the critical chain.
// ---------------------------------------------------------------------------
__global__ void __launch_bounds__(32) k3_scan(float* __restrict__ out)
{
    __shared__ float ks[RR];
    const int bt = blockIdx.x, lane = threadIdx.x;

    float ex[12], kh[12];
    #pragma unroll
    for (int j = 0; j < 12; j++) {
        int idx = j*32 + lane;
        ex[j] = (idx < RR) ? expf(g_scores[(size_t)bt*RR + idx]) : 0.0f;
        kh[j] = 0.0f;
    }

    #pragma unroll 1
    for (int it = 0; it < KSEL - 1; it++) {
        float z = (((ex[0] + ex[1]) + (ex[2] + ex[3])) +
                   ((ex[4] + ex[5]) + (ex[6] + ex[7]))) +
                  ((ex[8] + ex[9]) + (ex[10] + ex[11]));
        #pragma unroll
        for (int o = 16; o; o >>= 1) z += __shfl_xor_sync(0xffffffffu, z, o);
        float rinv = frcp(z);
        #pragma unroll
        for (int j = 0; j < 12; j++) {
            float oh = ex[j] * rinv;
            kh[j] += oh;
            ex[j] *= fmaxf(1.0f - oh, EPS_TINY);
        }
    }
    {   // final iteration: khot update only
        float z = (((ex[0] + ex[1]) + (ex[2] + ex[3])) +
                   ((ex[4] + ex[5]) + (ex[6] + ex[7]))) +
                  ((ex[8] + ex[9]) + (ex[10] + ex[11]));
        #pragma unroll
        for (int o = 16; o; o >>= 1) z += __shfl_xor_sync(0xffffffffu, z, o);
        float rinv = frcp(z);
        #pragma unroll
        for (int j = 0; j < 12; j++) kh[j] += ex[j] * rinv;
    }

    #pragma unroll
    for (int j = 0; j < 12; j++) {
        int idx = j*32 + lane;
        if (idx < RR) {
            out[(size_t)bt*RR + idx] = kh[j];
            ks[idx] = kh[j];
        }
    }
    __syncthreads();

    int rank[12];
    #pragma unroll
    for (int j = 0; j < 12; j++) rank[j] = 0;
    for (int i = 0; i < RR; i++) {
        float kv = ks[i];
        #pragma unroll
        for (int j = 0; j < 12; j++) {
            int idx = j*32 + lane;
            rank[j] += (kv > kh[j]) || (kv == kh[j] && i < idx);
        }
    }
    float* idx_out = out + (size_t)NROWS;
    #pragma unroll
    for (int j = 0; j < 12; j++) {
        int idx = j*32 + lane;
        if (idx < RR && rank[j] < KSEL)
            idx_out[(size_t)bt*KSEL + rank[j]] = (float)idx;
    }
}

// ---------------------------------------------------------------------------
extern "C" void kernel_launch(void* const* d_in, const int* in_sizes, int n_in,
                              void* d_out, int out_size)
{
    const float* x   = (const float*)d_in[0];
    const float* u   = (const float*)d_in[1];
    const float* lnw = (const float*)d_in[2];
    const float* lnb = (const float*)d_in[3];
    const float* w1  = (const float*)d_in[4];
    const float* b1  = (const float*)d_in[5];
    const float* w2  = (const float*)d_in[6];
    const float* b2  = (const float*)d_in[7];
    const float* w3  = (const float*)d_in[8];
    const float* b3  = (const float*)d_in[9];
    float* out = (float*)d_out;

    const size_t smem1 = (size_t)(128*130 + 128*132 + 2*64*16) * sizeof(float); // 142336 B
    cudaFuncSetAttribute(k1_ln_gemm1, cudaFuncAttributeMaxDynamicSharedMemorySize,
                         (int)smem1);

    k1_ln_gemm1<<<NBLK1, 256, smem1>>>(x, lnw, lnb, w1, b1);
    k_glob<<<BT, 64>>>(w2);
    k2_scores<<<NBLK1, 256>>>(w2, b2, w3, b3, u);
    k3_scan<<<BT, 32>>>(out);
}